// round 6
// baseline (speedup 1.0000x reference)
#include <cuda_runtime.h>

// GaussianBlur fused: depthwise 21x21 Gaussian (sigma=5), reflect pad 10,
// [32,3,512,512] fp32 -> 96 independent 512x512 images.
// Separable, single kernel: load tile+halo -> horizontal conv in-place in
// smem -> vertical conv in registers -> store. No gmem scratch round-trip.

#define W_ 512
#define H_ 512
#define NIMG 96
#define PAD 10

#define TX 256
#define TY 64
#define AROWS (TY + 2 * PAD)          // 84
#define ACOLS (TX + 2 * PAD)          // 276
#define SMEM_BYTES (AROWS * ACOLS * 4)  // 92736 bytes (dynamic smem)

// 1D separable weights (validated in the passing 2-pass kernel):
// exp(-(d^2)/50) / 12.089199128. Kept as function-local const + full unroll
// so ptxas folds them into FFMA immediate form (rt_SMSP=1).
#define KW_INIT const float KW[21] = { \
    0.01119473f, 0.01636989f, 0.02299883f, 0.03104516f, 0.04026340f, \
    0.05017128f, 0.06006594f, 0.06909227f, 0.07635877f, 0.08108053f, \
    0.08271847f, \
    0.08108053f, 0.07635877f, 0.06909227f, 0.06006594f, 0.05017128f, \
    0.04026340f, 0.03104516f, 0.02299883f, 0.01636989f, 0.01119473f }

__device__ __forceinline__ int reflect512(int i) {
    // jnp.pad mode="reflect": -k -> k, 511+k -> 511-k (single reflection)
    i = (i < 0) ? -i : i;
    return (i > 511) ? (1022 - i) : i;
}

extern __shared__ __align__(16) float A[];  // [AROWS][ACOLS]

__global__ __launch_bounds__(256, 2)
void blur_fused(const float* __restrict__ in, float* __restrict__ out) {
    KW_INIT;
    const int n   = blockIdx.z;
    const int x0  = blockIdx.x * TX;
    const int y0  = blockIdx.y * TY;
    const int tid = threadIdx.x;

    const float* __restrict__ img = in + (size_t)n * (H_ * W_);

    // ---- Phase 0: load input tile + halo (reflect) into smem, coalesced ----
    #pragma unroll 4
    for (int i = tid; i < AROWS * ACOLS; i += 256) {
        const int r  = i / ACOLS;
        const int c  = i - r * ACOLS;
        const int gy = reflect512(y0 - PAD + r);
        const int gx = reflect512(x0 - PAD + c);
        A[i] = img[gy * W_ + gx];
    }
    __syncthreads();

    // ---- Phase 1: horizontal 21-tap, in place. One warp per row. ----------
    // Lane l: reads aligned 28-float window [8l, 8l+27], computes 8 outputs,
    // writes them back over cols [8l, 8l+7]. Warp-exclusive row => only
    // __syncwarp needed between the reads and the overwrite.
    const int warp = tid >> 5;
    const int lane = tid & 31;
    #pragma unroll 1
    for (int r = warp; r < AROWS; r += 8) {
        float* row = A + r * ACOLS;
        float win[28];
        #pragma unroll
        for (int j = 0; j < 7; ++j) {
            float4 t = *reinterpret_cast<const float4*>(row + 8 * lane + 4 * j);
            win[4 * j + 0] = t.x; win[4 * j + 1] = t.y;
            win[4 * j + 2] = t.z; win[4 * j + 3] = t.w;
        }
        float h[8];
        #pragma unroll
        for (int j = 0; j < 8; ++j) {
            float a = 0.f;
            #pragma unroll
            for (int k = 0; k < 21; ++k)
                a = fmaf(KW[k], win[j + k], a);
            h[j] = a;
        }
        __syncwarp();
        *reinterpret_cast<float4*>(row + 8 * lane)     = make_float4(h[0], h[1], h[2], h[3]);
        *reinterpret_cast<float4*>(row + 8 * lane + 4) = make_float4(h[4], h[5], h[6], h[7]);
    }
    __syncthreads();

    // ---- Phase 2: vertical 21-tap from smem, register window. -------------
    // Thread owns column c; 2 strips of 32 outputs from a 52-row window
    // (1.625 smem loads per output). Conflict-free (consecutive lanes ->
    // consecutive addresses), stores coalesced per warp-row.
    float* __restrict__ outimg = out + (size_t)n * (H_ * W_);
    const int c = tid;  // 0..255
    #pragma unroll 1
    for (int s = 0; s < 2; ++s) {
        const int ybase = s * 32;
        float v[52];
        #pragma unroll
        for (int j = 0; j < 52; ++j)
            v[j] = A[(ybase + j) * ACOLS + c];
        #pragma unroll
        for (int rr = 0; rr < 32; ++rr) {
            float a = 0.f;
            #pragma unroll
            for (int k = 0; k < 21; ++k)
                a = fmaf(KW[k], v[rr + k], a);
            outimg[(size_t)(y0 + ybase + rr) * W_ + x0 + c] = a;
        }
    }
}

extern "C" void kernel_launch(void* const* d_in, const int* in_sizes, int n_in,
                              void* d_out, int out_size) {
    const float* x = (const float*)d_in[0];
    float* out = (float*)d_out;
    (void)in_sizes; (void)n_in; (void)out_size;

    // 92.7 KB dynamic smem > 48 KB static limit -> opt in every call
    // (idempotent, not a stream op, safe under graph capture).
    cudaFuncSetAttribute(blur_fused,
                         cudaFuncAttributeMaxDynamicSharedMemorySize, SMEM_BYTES);

    // grid: 2 x-tiles, 8 y-tiles, 96 images = 1536 blocks
    blur_fused<<<dim3(2, 8, NIMG), 256, SMEM_BYTES>>>(x, out);
}

// round 7
// speedup vs baseline: 1.8054x; 1.8054x over previous
#include <cuda_runtime.h>

// GaussianBlur fused v2: depthwise 21x21 Gaussian (sigma=5), reflect pad 10,
// [32,3,512,512] fp32 -> 96 independent 512x512 images.
// Single kernel, NO raw-tile smem stage:
//   phase 1: horizontal 21-tap straight from gmem (aligned float4 windows,
//            x-overlap served by L1) -> h-result into 43KB static smem
//   phase 2: vertical 21-tap from smem (register window) -> gmem
// Tile: 128 wide x 64 tall outputs; h-result covers 84 rows (y halo).

#define W_ 512
#define H_ 512
#define NIMG 96
#define PAD 10

#define TX 128
#define TY 64
#define HROWS (TY + 2 * PAD)   // 84 h-result rows per tile

// 1D separable weights (validated): exp(-(d^2)/50) / 12.089199128
#define KW_INIT const float KW[21] = { \
    0.01119473f, 0.01636989f, 0.02299883f, 0.03104516f, 0.04026340f, \
    0.05017128f, 0.06006594f, 0.06909227f, 0.07635877f, 0.08108053f, \
    0.08271847f, \
    0.08108053f, 0.07635877f, 0.06909227f, 0.06006594f, 0.05017128f, \
    0.04026340f, 0.03104516f, 0.02299883f, 0.01636989f, 0.01119473f }

__device__ __forceinline__ int reflect512(int i) {
    // jnp.pad mode="reflect": -k -> k, 511+k -> 511-k (single reflection)
    i = (i < 0) ? -i : i;
    return (i > 511) ? (1022 - i) : i;
}

__global__ __launch_bounds__(256, 4)
void blur_fused2(const float* __restrict__ in, float* __restrict__ out) {
    KW_INIT;
    __shared__ __align__(16) float Hs[HROWS * TX];   // 84*128*4 = 43008 B

    const int n   = blockIdx.z;
    const int x0  = blockIdx.x * TX;
    const int y0  = blockIdx.y * TY;
    const int tid = threadIdx.x;

    const float* __restrict__ img = in + (size_t)n * (H_ * W_);

    // ---- Phase 1: horizontal conv, gmem -> smem ---------------------------
    // Task j -> row r = j>>4 (0..83), group g = j&15. Thread computes the 8
    // outputs [8g .. 8g+7] of h-row r from a 32-float window starting at
    // x = x0 + 8g - 12 (16B-aligned). Output 8g+t needs win[t+2 .. t+22].
    for (int j = tid; j < HROWS * (TX / 8); j += 256) {
        const int r  = j >> 4;
        const int g  = j & 15;
        const int gy = reflect512(y0 - PAD + r);
        const int xb = x0 + 8 * g - 12;
        const float* __restrict__ rowp = img + gy * W_;

        float win[32];
        if (xb >= 0 && xb + 31 < W_) {           // aligned fast path
            #pragma unroll
            for (int q = 0; q < 8; ++q) {
                float4 t = *reinterpret_cast<const float4*>(rowp + xb + 4 * q);
                win[4 * q + 0] = t.x; win[4 * q + 1] = t.y;
                win[4 * q + 2] = t.z; win[4 * q + 3] = t.w;
            }
        } else {                                  // x-border: scalar reflect
            #pragma unroll
            for (int q = 0; q < 32; ++q)
                win[q] = rowp[reflect512(xb + q)];
        }

        float h[8];
        #pragma unroll
        for (int t = 0; t < 8; ++t) {
            float a = 0.f;
            #pragma unroll
            for (int k = 0; k < 21; ++k)
                a = fmaf(KW[k], win[t + 2 + k], a);
            h[t] = a;
        }
        float* dst = Hs + r * TX + 8 * g;
        *reinterpret_cast<float4*>(dst)     = make_float4(h[0], h[1], h[2], h[3]);
        *reinterpret_cast<float4*>(dst + 4) = make_float4(h[4], h[5], h[6], h[7]);
    }
    __syncthreads();

    // ---- Phase 2: vertical conv, smem -> gmem -----------------------------
    // Thread owns column c = tid&127; half = tid>>7 picks rows [0,32) or
    // [32,64). Two 16-row sub-strips with a 36-row register window keep
    // regs under the 64-reg / 4-CTA cap.
    float* __restrict__ outimg = out + (size_t)n * (H_ * W_);
    const int c    = tid & 127;
    const int half = tid >> 7;

    #pragma unroll
    for (int sub = 0; sub < 2; ++sub) {
        const int ybase = half * 32 + sub * 16;
        float v[36];
        #pragma unroll
        for (int q = 0; q < 36; ++q)
            v[q] = Hs[(ybase + q) * TX + c];
        #pragma unroll
        for (int rr = 0; rr < 16; ++rr) {
            float a = 0.f;
            #pragma unroll
            for (int k = 0; k < 21; ++k)
                a = fmaf(KW[k], v[rr + k], a);
            outimg[(size_t)(y0 + ybase + rr) * W_ + x0 + c] = a;
        }
    }
}

extern "C" void kernel_launch(void* const* d_in, const int* in_sizes, int n_in,
                              void* d_out, int out_size) {
    const float* x = (const float*)d_in[0];
    float* out = (float*)d_out;
    (void)in_sizes; (void)n_in; (void)out_size;

    // 4 x-tiles, 8 y-tiles, 96 images = 3072 blocks of 256 threads
    blur_fused2<<<dim3(W_ / TX, H_ / TY, NIMG), 256>>>(x, out);
}

// round 8
// speedup vs baseline: 2.4580x; 1.3615x over previous
#include <cuda_runtime.h>

// GaussianBlur v3 (vertical-first): depthwise 21x21 Gaussian (sigma=5),
// reflect pad 10, [32,3,512,512] fp32 = 96 independent 512x512 images.
// Single kernel per tile (128 wide x 64 tall):
//   phase 1: VERTICAL 21-tap from gmem. Dense column loads (no l1tex
//            wavefront amplification), register window, result -> 37KB smem.
//   phase 2: HORIZONTAL 21-tap from smem. 4-output windows (6x LDS.128,
//            start-stride 4 floats => conflict-free banking), dense STG.

#define W_ 512
#define H_ 512
#define NIMG 96
#define PAD 10

#define TX 128
#define TY 64
#define VCOLS   148            // TX + 2*PAD (x halo for the h-pass)
#define VSTRIDE 148            // floats; 592 B per row, 16B-aligned
#define QROWS   16             // v-pass rows per task
#define VWIN    (QROWS + 2 * PAD)   // 36
#define NTASK1  (VCOLS * (TY / QROWS))  // 148*4 = 592

// 1D separable weights (validated): exp(-(d^2)/50) / 12.089199128
#define KW_INIT const float KW[21] = { \
    0.01119473f, 0.01636989f, 0.02299883f, 0.03104516f, 0.04026340f, \
    0.05017128f, 0.06006594f, 0.06909227f, 0.07635877f, 0.08108053f, \
    0.08271847f, \
    0.08108053f, 0.07635877f, 0.06909227f, 0.06006594f, 0.05017128f, \
    0.04026340f, 0.03104516f, 0.02299883f, 0.01636989f, 0.01119473f }

__device__ __forceinline__ int reflect512(int i) {
    // jnp.pad mode="reflect": -k -> k, 511+k -> 511-k (single reflection)
    i = (i < 0) ? -i : i;
    return (i > 511) ? (1022 - i) : i;
}

__global__ __launch_bounds__(256, 5)
void blur_v3(const float* __restrict__ in, float* __restrict__ out) {
    KW_INIT;
    __shared__ __align__(16) float Vs[TY * VSTRIDE];   // 37888 B

    const int n   = blockIdx.z;
    const int x0  = blockIdx.x * TX;
    const int y0  = blockIdx.y * TY;
    const int tid = threadIdx.x;

    const float* __restrict__ img = in + (size_t)n * (H_ * W_);

    // ---- Phase 1: vertical conv, gmem -> Vs -------------------------------
    // Task tau -> (quarter q = tau/148, col c = tau%148). Consecutive threads
    // get consecutive c => dense, coalesced column loads.
    #pragma unroll
    for (int it = 0; it < 3; ++it) {
        const int tau = tid + it * 256;
        if (tau < NTASK1) {
            const int q  = tau / VCOLS;
            const int c  = tau - q * VCOLS;
            const int gx = reflect512(x0 - PAD + c);
            const int yb = y0 + q * QROWS - PAD;   // first window row (global)

            float v[VWIN];
            if (yb >= 0 && yb + VWIN - 1 < H_) {   // interior: strided direct
                const float* __restrict__ p = img + (size_t)yb * W_ + gx;
                #pragma unroll
                for (int j = 0; j < VWIN; ++j)
                    v[j] = p[j * W_];
            } else {                                // y-border: reflect rows
                #pragma unroll
                for (int j = 0; j < VWIN; ++j)
                    v[j] = img[(size_t)reflect512(yb + j) * W_ + gx];
            }

            float* __restrict__ dst = Vs + (q * QROWS) * VSTRIDE + c;
            #pragma unroll
            for (int rr = 0; rr < QROWS; ++rr) {
                float a = 0.f;
                #pragma unroll
                for (int k = 0; k < 21; ++k)
                    a = fmaf(KW[k], v[rr + k], a);
                dst[rr * VSTRIDE] = a;             // conflict-free STS
            }
        }
    }
    __syncthreads();

    // ---- Phase 2: horizontal conv, Vs -> gmem -----------------------------
    // Task tau -> (row r = tau>>5, group g = tau&31). Warp = one row, lanes
    // along x. Window = Vs[r][4g .. 4g+23]: 6x LDS.128, start addr
    // 592r + 16g bytes (16B aligned); per 8-lane phase banks {4g..4g+3}
    // cover all 32 banks -> conflict-free. STG.128 dense.
    float* __restrict__ outimg = out + (size_t)n * (H_ * W_);
    const int g  = tid & 31;          // lane = x-group, fixed per thread
    const int r0 = tid >> 5;          // warp id = starting row

    #pragma unroll
    for (int i = 0; i < 8; ++i) {
        const int r = r0 + i * 8;
        const float* __restrict__ src = Vs + r * VSTRIDE + 4 * g;

        float wv[24];
        #pragma unroll
        for (int j = 0; j < 6; ++j) {
            float4 t = *reinterpret_cast<const float4*>(src + 4 * j);
            wv[4 * j + 0] = t.x; wv[4 * j + 1] = t.y;
            wv[4 * j + 2] = t.z; wv[4 * j + 3] = t.w;
        }

        float h0 = 0.f, h1 = 0.f, h2 = 0.f, h3 = 0.f;
        #pragma unroll
        for (int k = 0; k < 21; ++k) {
            const float w = KW[k];
            h0 = fmaf(w, wv[k + 0], h0);
            h1 = fmaf(w, wv[k + 1], h1);
            h2 = fmaf(w, wv[k + 2], h2);
            h3 = fmaf(w, wv[k + 3], h3);
        }
        *reinterpret_cast<float4*>(outimg + (size_t)(y0 + r) * W_ + x0 + 4 * g)
            = make_float4(h0, h1, h2, h3);
    }
}

extern "C" void kernel_launch(void* const* d_in, const int* in_sizes, int n_in,
                              void* d_out, int out_size) {
    const float* x = (const float*)d_in[0];
    float* out = (float*)d_out;
    (void)in_sizes; (void)n_in; (void)out_size;

    // 4 x-tiles, 8 y-tiles, 96 images = 3072 blocks of 256 threads
    blur_v3<<<dim3(W_ / TX, H_ / TY, NIMG), 256>>>(x, out);
}